// round 13
// baseline (speedup 1.0000x reference)
#include <cuda_runtime.h>
#include <cuda_fp16.h>
#include <stdint.h>

#define N_NODES 50000
#define N_EDGES 800000
#define DIM 128
#define KPI 0.62831853071795865f
#define FULL 0xffffffffu
#define QNB 32
#define QPITCH 136
#define QP_SMEM ((128 * QPITCH + 2 * QNB * QPITCH) * 4)
#define EPITCH 136
#define UPITCH 132
#define KE_SMEM ((4 * 16 * EPITCH + 4 * 8 * UPITCH + 4 * 128 + 32) * 4)

// ---- scratch ----
__device__ __half2 g_Ph[(size_t)N_NODES * 512];  // [n][h][64xhalf2], pre-scaled by 0.25
__device__ float g_c[N_NODES * 8];               // (q.b_K)*0.25
__device__ float g_WKT[DIM * DIM];
__device__ int   g_counts[N_NODES];
__device__ int   g_offsets[N_NODES + 1];
__device__ int   g_cursor[N_NODES];
__device__ int2  g_pe[N_EDGES];                  // (edge, phi bits) CSR order

__device__ __forceinline__ uint32_t f2tf(float f) {
    uint32_t o;
    asm("cvt.rna.tf32.f32 %0, %1;" : "=r"(o) : "f"(f));
    return o;
}
__device__ __forceinline__ void mma_tf32(float c[4], uint32_t a0, uint32_t a1,
                                         uint32_t a2, uint32_t a3,
                                         uint32_t b0, uint32_t b1) {
    asm volatile(
        "mma.sync.aligned.m16n8k8.row.col.f32.tf32.tf32.f32 "
        "{%0,%1,%2,%3}, {%4,%5,%6,%7}, {%8,%9}, {%0,%1,%2,%3};"
        : "+f"(c[0]), "+f"(c[1]), "+f"(c[2]), "+f"(c[3])
        : "r"(a0), "r"(a1), "r"(a2), "r"(a3), "r"(b0), "r"(b1));
}

// ---- CSR build ----
__global__ void k_zero() {
    int i = blockIdx.x * blockDim.x + threadIdx.x;
    if (i < N_NODES) g_counts[i] = 0;
}
__global__ void k_hist(const int* __restrict__ ei) {
    int e = blockIdx.x * blockDim.x + threadIdx.x;
    if (e < N_EDGES) atomicAdd(&g_counts[ei[N_EDGES + e]], 1);
}
__global__ void k_scan() {
    __shared__ int wsum[32];
    int t = threadIdx.x, lane = t & 31, wid = t >> 5;
    int carry = 0;
    for (int base = 0; base < N_NODES; base += 1024) {
        int i = base + t;
        int v = (i < N_NODES) ? g_counts[i] : 0;
        int x = v;
        #pragma unroll
        for (int o = 1; o < 32; o <<= 1) { int y = __shfl_up_sync(FULL, x, o); if (lane >= o) x += y; }
        if (lane == 31) wsum[wid] = x;
        __syncthreads();
        if (wid == 0) {
            int s = wsum[lane];
            #pragma unroll
            for (int o = 1; o < 32; o <<= 1) { int y = __shfl_up_sync(FULL, s, o); if (lane >= o) s += y; }
            wsum[lane] = s;
        }
        __syncthreads();
        int excl = x - v + (wid ? wsum[wid - 1] : 0);
        if (i < N_NODES) { g_offsets[i] = carry + excl; g_cursor[i] = carry + excl; }
        carry += wsum[31];
        __syncthreads();
    }
    if (t == 0) g_offsets[N_NODES] = carry;
}
__global__ void k_scatter(const int* __restrict__ ei, const float* __restrict__ elen) {
    int e = blockIdx.x * blockDim.x + threadIdx.x;
    if (e < N_EDGES) {
        int j = ei[N_EDGES + e];
        int pos = atomicAdd(&g_cursor[j], 1);
        float phi = fmaf(0.5f, __cosf(elen[e] * KPI), 0.5f);
        g_pe[pos] = make_int2(e, __float_as_int(phi));
    }
}
__global__ void k_wkt(const float* __restrict__ WK) {
    int i = blockIdx.x * blockDim.x + threadIdx.x;
    if (i < DIM * DIM) g_WKT[(i % DIM) * DIM + (i / DIM)] = WK[i];
}

// ---- node precompute on tensor cores (tf32): q = xWQ+bQ; P_h = q_h @ WKT_h ----
__global__ void __launch_bounds__(128) k_qp(
    const float* __restrict__ x, const float* __restrict__ WQ,
    const float* __restrict__ bQ, const float* __restrict__ bK)
{
    extern __shared__ uint32_t sm[];
    uint32_t* s_w = sm;
    uint32_t* s_x = sm + 128 * QPITCH;
    uint32_t* s_q = s_x + QNB * QPITCH;
    int tid = threadIdx.x, lane = tid & 31, wp = tid >> 5;
    int g = lane >> 2, tg = lane & 3;
    int nb0 = blockIdx.x * QNB;
    int wbase = wp * 32;

    #pragma unroll
    for (int it = 0; it < 8; it++) {
        int idx = tid + it * 128;
        int row = idx >> 5, c4 = (idx & 31) * 4;
        int node = nb0 + row;
        float4 v = make_float4(0.f, 0.f, 0.f, 0.f);
        if (node < N_NODES) v = *reinterpret_cast<const float4*>(x + (size_t)node * DIM + c4);
        s_x[row * QPITCH + c4 + 0] = f2tf(v.x);
        s_x[row * QPITCH + c4 + 1] = f2tf(v.y);
        s_x[row * QPITCH + c4 + 2] = f2tf(v.z);
        s_x[row * QPITCH + c4 + 3] = f2tf(v.w);
    }
    #pragma unroll 8
    for (int it = 0; it < 32; it++) {
        int idx = tid + it * 128;
        int row = idx >> 5, c4 = (idx & 31) * 4;
        float4 v = *reinterpret_cast<const float4*>(WQ + row * DIM + c4);
        s_w[row * QPITCH + c4 + 0] = f2tf(v.x);
        s_w[row * QPITCH + c4 + 1] = f2tf(v.y);
        s_w[row * QPITCH + c4 + 2] = f2tf(v.z);
        s_w[row * QPITCH + c4 + 3] = f2tf(v.w);
    }
    __syncthreads();

    #pragma unroll
    for (int mt = 0; mt < 2; mt++) {
        float c[4][4];
        #pragma unroll
        for (int nt = 0; nt < 4; nt++) {
            int col = wbase + nt * 8 + 2 * tg;
            c[nt][0] = bQ[col]; c[nt][1] = bQ[col + 1];
            c[nt][2] = c[nt][0]; c[nt][3] = c[nt][1];
        }
        #pragma unroll
        for (int kt = 0; kt < 16; kt++) {
            int ra = (mt * 16 + g) * QPITCH + kt * 8 + tg;
            int rb = (mt * 16 + g + 8) * QPITCH + kt * 8 + tg;
            uint32_t a0 = s_x[ra], a1 = s_x[rb], a2 = s_x[ra + 4], a3 = s_x[rb + 4];
            #pragma unroll
            for (int nt = 0; nt < 4; nt++) {
                int cb = wbase + nt * 8 + g;
                uint32_t b0 = s_w[(kt * 8 + tg) * QPITCH + cb];
                uint32_t b1 = s_w[(kt * 8 + tg + 4) * QPITCH + cb];
                mma_tf32(c[nt], a0, a1, a2, a3, b0, b1);
            }
        }
        #pragma unroll
        for (int nt = 0; nt < 4; nt++) {
            int col = wbase + nt * 8 + 2 * tg;
            s_q[(mt * 16 + g) * QPITCH + col]         = f2tf(c[nt][0]);
            s_q[(mt * 16 + g) * QPITCH + col + 1]     = f2tf(c[nt][1]);
            s_q[(mt * 16 + g + 8) * QPITCH + col]     = f2tf(c[nt][2]);
            s_q[(mt * 16 + g + 8) * QPITCH + col + 1] = f2tf(c[nt][3]);
        }
    }
    __syncthreads();

    #pragma unroll 8
    for (int it = 0; it < 32; it++) {
        int idx = tid + it * 128;
        int row = idx >> 5, c4 = (idx & 31) * 4;
        float4 v = *reinterpret_cast<const float4*>(g_WKT + row * DIM + c4);
        s_w[row * QPITCH + c4 + 0] = f2tf(v.x);
        s_w[row * QPITCH + c4 + 1] = f2tf(v.y);
        s_w[row * QPITCH + c4 + 2] = f2tf(v.z);
        s_w[row * QPITCH + c4 + 3] = f2tf(v.w);
    }
    #pragma unroll
    for (int it = 0; it < 2; it++) {
        int item = tid + it * 128;
        int i = item >> 3, h = item & 7;
        int node = nb0 + i;
        if (node < N_NODES) {
            float cc = 0.f;
            #pragma unroll
            for (int k = 0; k < 16; k++)
                cc = fmaf(__uint_as_float(s_q[i * QPITCH + h * 16 + k]), bK[h * 16 + k], cc);
            g_c[node * 8 + h] = cc * 0.25f;
        }
    }
    __syncthreads();

    #pragma unroll
    for (int mt = 0; mt < 2; mt++) {
        int node0 = nb0 + mt * 16 + g, node1 = node0 + 8;
        #pragma unroll
        for (int h = 0; h < 8; h++) {
            float c[4][4];
            #pragma unroll
            for (int nt = 0; nt < 4; nt++)
                c[nt][0] = c[nt][1] = c[nt][2] = c[nt][3] = 0.f;
            #pragma unroll
            for (int kt = 0; kt < 2; kt++) {
                int qa = (mt * 16 + g) * QPITCH + h * 16 + kt * 8 + tg;
                int qb = (mt * 16 + g + 8) * QPITCH + h * 16 + kt * 8 + tg;
                uint32_t a0 = s_q[qa], a1 = s_q[qb], a2 = s_q[qa + 4], a3 = s_q[qb + 4];
                #pragma unroll
                for (int nt = 0; nt < 4; nt++) {
                    int cb = wbase + nt * 8 + g;
                    uint32_t b0 = s_w[(h * 16 + kt * 8 + tg) * QPITCH + cb];
                    uint32_t b1 = s_w[(h * 16 + kt * 8 + tg + 4) * QPITCH + cb];
                    mma_tf32(c[nt], a0, a1, a2, a3, b0, b1);
                }
            }
            if (node0 < N_NODES) {
                #pragma unroll
                for (int nt = 0; nt < 4; nt++) {
                    int c2 = wp * 16 + nt * 4 + tg;
                    g_Ph[(size_t)node0 * 512 + h * 64 + c2] =
                        __floats2half2_rn(0.25f * c[nt][0], 0.25f * c[nt][1]);
                }
            }
            if (node1 < N_NODES) {
                #pragma unroll
                for (int nt = 0; nt < 4; nt++) {
                    int c2 = wp * 16 + nt * 4 + tg;
                    g_Ph[(size_t)node1 * 512 + h * 64 + c2] =
                        __floats2half2_rn(0.25f * c[nt][2], 0.25f * c[nt][3]);
                }
            }
        }
    }
}

// ---- fused edge pass: 16-edge tf32 mma tiles (warp=node, 4 nodes/block) ----
__global__ void __launch_bounds__(128, 4) k_edge(
    const float4* __restrict__ ea4,
    const float* __restrict__ WV, const float* __restrict__ bV,
    const float* __restrict__ WO, const float* __restrict__ bO,
    float* __restrict__ out)
{
    extern __shared__ uint32_t esm[];
    uint32_t* s_a  = esm;                        // [4][16][EPITCH] edge tiles (tf32)
    float*    s_sU = (float*)(esm + 4 * 16 * EPITCH);  // [4][8][UPITCH] (also w-bounce scratch)
    float*    s_no = s_sU + 4 * 8 * UPITCH;      // [4][128]
    float*    s_sT = s_no + 4 * 128;             // [4][8]

    int tid = threadIdx.x, w = tid >> 5, l = tid & 31;
    int g = l >> 2, tg = l & 3;
    int n = blockIdx.x * 4 + w;
    uint32_t* aT = s_a + w * 16 * EPITCH;
    float* wsc = s_sU + w * 8 * UPITCH;          // [16][9] scratch during loop

    // P as score-GEMM B-fragments: this lane serves head g, k-dims tg(+4) per k-step
    uint32_t Pb0[16], Pb1[16];
    {
        const __half* ph = reinterpret_cast<const __half*>(g_Ph + (size_t)n * 512) + g * 128;
        #pragma unroll
        for (int kt = 0; kt < 16; kt++) {
            Pb0[kt] = f2tf(__half2float(ph[kt * 8 + tg]));
            Pb1[kt] = f2tf(__half2float(ph[kt * 8 + tg + 4]));
        }
    }
    float ch0 = g_c[n * 8 + 2 * tg], ch1 = g_c[n * 8 + 2 * tg + 1];

    float U[8][4];
    #pragma unroll
    for (int mt = 0; mt < 8; mt++) { U[mt][0] = 0.f; U[mt][1] = 0.f; U[mt][2] = 0.f; U[mt][3] = 0.f; }
    float ss0 = 0.f, ss1 = 0.f, ts0 = 0.f, ts1 = 0.f;

    int beg = g_offsets[n], end = g_offsets[n + 1];
    int r = l >> 1, half = l & 1;

    for (int tb = beg; tb < end; tb += 16) {
        // edge ids + phi for this tile (lanes 0..15 hold slot l)
        int2 pe = make_int2(0, 0);
        if (l < 16 && tb + l < end) pe = g_pe[tb + l];

        // gather 16 edge rows: lane pair (2r,2r+1) loads row r, cvt.rna to tf32
        int erow = __shfl_sync(FULL, pe.x, r);
        bool rvalid = (tb + r < end);
        const float4* src = ea4 + (size_t)erow * 32 + half;
        #pragma unroll
        for (int k = 0; k < 16; k++) {
            float4 v = make_float4(0.f, 0.f, 0.f, 0.f);
            if (rvalid) v = __ldcs(src + 2 * k);
            uint4 tv = make_uint4(f2tf(v.x), f2tf(v.y), f2tf(v.z), f2tf(v.w));
            *reinterpret_cast<uint4*>(aT + r * EPITCH + (half + 2 * k) * 4) = tv;
        }
        __syncwarp();

        // score GEMM: S[16e,8h] = A @ P
        float c[4] = {0.f, 0.f, 0.f, 0.f};
        #pragma unroll
        for (int kt = 0; kt < 16; kt++) {
            int ra = g * EPITCH + kt * 8 + tg;
            int rb = (g + 8) * EPITCH + kt * 8 + tg;
            mma_tf32(c, aT[ra], aT[rb], aT[ra + 4], aT[rb + 4], Pb0[kt], Pb1[kt]);
        }

        // softmax numerators: lane holds edges g,g+8 x heads 2tg,2tg+1
        float phiA = __int_as_float(__shfl_sync(FULL, pe.y, g));
        float phiB = __int_as_float(__shfl_sync(FULL, pe.y, g + 8));
        bool vA = (tb + g < end), vB = (tb + g + 8 < end);
        float ex0 = __expf(c[0] + ch0), ex1 = __expf(c[1] + ch1);
        float ex2 = __expf(c[2] + ch0), ex3 = __expf(c[3] + ch1);
        float w0 = ex0 * phiA, w1 = ex1 * phiA, w2 = ex2 * phiB, w3 = ex3 * phiB;
        if (vA) { ss0 += ex0; ss1 += ex1; }
        if (vB) { ss0 += ex2; ss1 += ex3; }
        ts0 += w0 + w2; ts1 += w1 + w3;

        // bounce w[e,h] to smem for U-GEMM B-fragments
        wsc[g * 9 + 2 * tg] = w0;
        wsc[g * 9 + 2 * tg + 1] = w1;
        wsc[(g + 8) * 9 + 2 * tg] = w2;
        wsc[(g + 8) * 9 + 2 * tg + 1] = w3;
        __syncwarp();

        // U GEMM: U[128d,8h] += A^T @ W   (8 m-tiles x 2 k-steps)
        #pragma unroll
        for (int ks = 0; ks < 2; ks++) {
            uint32_t b0 = f2tf(wsc[(ks * 8 + tg) * 9 + g]);
            uint32_t b1 = f2tf(wsc[(ks * 8 + tg + 4) * 9 + g]);
            int e0 = (ks * 8 + tg) * EPITCH, e1 = (ks * 8 + tg + 4) * EPITCH;
            #pragma unroll
            for (int mt = 0; mt < 8; mt++) {
                int d0 = mt * 16 + g;
                mma_tf32(U[mt], aT[e0 + d0], aT[e0 + d0 + 8], aT[e1 + d0], aT[e1 + d0 + 8], b0, b1);
            }
        }
        __syncwarp();  // aT/wsc reused next tile
    }

    // reduce ssum/tsum over edge-lanes (g axis); lane keeps heads 2tg,2tg+1
    #pragma unroll
    for (int off = 4; off <= 16; off <<= 1) {
        ss0 += __shfl_xor_sync(FULL, ss0, off);
        ss1 += __shfl_xor_sync(FULL, ss1, off);
        ts0 += __shfl_xor_sync(FULL, ts0, off);
        ts1 += __shfl_xor_sync(FULL, ts1, off);
    }
    float iv0 = (ss0 > 0.f) ? (1.f / ss0) : 0.f;
    float iv1 = (ss1 > 0.f) ? (1.f / ss1) : 0.f;
    if (l < 4) { s_sT[w * 8 + 2 * tg] = ts0 * iv0; s_sT[w * 8 + 2 * tg + 1] = ts1 * iv1; }
    __syncwarp();

    // store normalized U: C-frag (g,tg) holds U[d=mt16+g(+8)][h=2tg(+1)]
    #pragma unroll
    for (int mt = 0; mt < 8; mt++) {
        int d = mt * 16 + g;
        s_sU[(w * 8 + 2 * tg) * UPITCH + d]         = U[mt][0] * iv0;
        s_sU[(w * 8 + 2 * tg + 1) * UPITCH + d]     = U[mt][1] * iv1;
        s_sU[(w * 8 + 2 * tg) * UPITCH + d + 8]     = U[mt][2] * iv0;
        s_sU[(w * 8 + 2 * tg + 1) * UPITCH + d + 8] = U[mt][3] * iv1;
    }
    __syncthreads();

    // GEMM1: node_out[n,c] = sum_d Unorm[n,h(c),d]*WV[d,c] + sT[n,h(c)]*bV[c]
    int c = tid, h = c >> 4;
    {
        float bv = bV[c];
        float a0c = s_sT[0 * 8 + h] * bv, a1c = s_sT[1 * 8 + h] * bv;
        float a2c = s_sT[2 * 8 + h] * bv, a3c = s_sT[3 * 8 + h] * bv;
        const float4* u0 = reinterpret_cast<const float4*>(s_sU + (0 * 8 + h) * UPITCH);
        const float4* u1 = reinterpret_cast<const float4*>(s_sU + (1 * 8 + h) * UPITCH);
        const float4* u2 = reinterpret_cast<const float4*>(s_sU + (2 * 8 + h) * UPITCH);
        const float4* u3 = reinterpret_cast<const float4*>(s_sU + (3 * 8 + h) * UPITCH);
        #pragma unroll 8
        for (int d4 = 0; d4 < 32; d4++) {
            float w0 = WV[(4 * d4 + 0) * DIM + c];
            float w1 = WV[(4 * d4 + 1) * DIM + c];
            float w2 = WV[(4 * d4 + 2) * DIM + c];
            float w3 = WV[(4 * d4 + 3) * DIM + c];
            float4 v;
            v = u0[d4]; a0c = fmaf(v.x, w0, fmaf(v.y, w1, fmaf(v.z, w2, fmaf(v.w, w3, a0c))));
            v = u1[d4]; a1c = fmaf(v.x, w0, fmaf(v.y, w1, fmaf(v.z, w2, fmaf(v.w, w3, a1c))));
            v = u2[d4]; a2c = fmaf(v.x, w0, fmaf(v.y, w1, fmaf(v.z, w2, fmaf(v.w, w3, a2c))));
            v = u3[d4]; a3c = fmaf(v.x, w0, fmaf(v.y, w1, fmaf(v.z, w2, fmaf(v.w, w3, a3c))));
        }
        s_no[0 * 128 + c] = a0c; s_no[1 * 128 + c] = a1c;
        s_no[2 * 128 + c] = a2c; s_no[3 * 128 + c] = a3c;
    }
    __syncthreads();

    // GEMM2: out = node_out @ W_O + b_O
    {
        float bo = bO[c];
        float o0 = bo, o1 = bo, o2 = bo, o3 = bo;
        const float4* v0 = reinterpret_cast<const float4*>(s_no + 0 * 128);
        const float4* v1 = reinterpret_cast<const float4*>(s_no + 1 * 128);
        const float4* v2 = reinterpret_cast<const float4*>(s_no + 2 * 128);
        const float4* v3 = reinterpret_cast<const float4*>(s_no + 3 * 128);
        #pragma unroll 8
        for (int d4 = 0; d4 < 32; d4++) {
            float w0 = WO[(4 * d4 + 0) * DIM + c];
            float w1 = WO[(4 * d4 + 1) * DIM + c];
            float w2 = WO[(4 * d4 + 2) * DIM + c];
            float w3 = WO[(4 * d4 + 3) * DIM + c];
            float4 v;
            v = v0[d4]; o0 = fmaf(v.x, w0, fmaf(v.y, w1, fmaf(v.z, w2, fmaf(v.w, w3, o0))));
            v = v1[d4]; o1 = fmaf(v.x, w0, fmaf(v.y, w1, fmaf(v.z, w2, fmaf(v.w, w3, o1))));
            v = v2[d4]; o2 = fmaf(v.x, w0, fmaf(v.y, w1, fmaf(v.z, w2, fmaf(v.w, w3, o2))));
            v = v3[d4]; o3 = fmaf(v.x, w0, fmaf(v.y, w1, fmaf(v.z, w2, fmaf(v.w, w3, o3))));
        }
        size_t base = (size_t)blockIdx.x * 4;
        out[(base + 0) * DIM + c] = o0;
        out[(base + 1) * DIM + c] = o1;
        out[(base + 2) * DIM + c] = o2;
        out[(base + 3) * DIM + c] = o3;
    }
}

extern "C" void kernel_launch(void* const* d_in, const int* in_sizes, int n_in,
                              void* d_out, int out_size) {
    const float* x    = (const float*)d_in[0];
    const int*   ei   = (const int*)  d_in[1];
    const float* ea   = (const float*)d_in[2];
    const float* elen = (const float*)d_in[3];
    const float* WQ   = (const float*)d_in[4];
    const float* bQ   = (const float*)d_in[5];
    const float* WK   = (const float*)d_in[6];
    const float* bK   = (const float*)d_in[7];
    const float* WV   = (const float*)d_in[8];
    const float* bV   = (const float*)d_in[9];
    const float* WO   = (const float*)d_in[10];
    const float* bO   = (const float*)d_in[11];
    float* out = (float*)d_out;

    static bool attr_set = false;
    if (!attr_set) {
        cudaFuncSetAttribute(k_qp, cudaFuncAttributeMaxDynamicSharedMemorySize, QP_SMEM);
        cudaFuncSetAttribute(k_edge, cudaFuncAttributeMaxDynamicSharedMemorySize, KE_SMEM);
        attr_set = true;
    }

    k_zero<<<(N_NODES + 255) / 256, 256>>>();
    k_hist<<<(N_EDGES + 255) / 256, 256>>>(ei);
    k_scan<<<1, 1024>>>();
    k_scatter<<<(N_EDGES + 255) / 256, 256>>>(ei, elen);
    k_wkt<<<(DIM * DIM + 255) / 256, 256>>>(WK);
    k_qp<<<(N_NODES + QNB - 1) / QNB, 128, QP_SMEM>>>(x, WQ, bQ, bK);
    k_edge<<<N_NODES / 4, 128, KE_SMEM>>>((const float4*)ea, WV, bV, WO, bO, out);
}